// round 3
// baseline (speedup 1.0000x reference)
#include <cuda_runtime.h>

// ---------------------------------------------------------------------------
// FullGraphModel — analytic form (see round-2 derivation).
//
// pooled = mean over M of where(v!=0, (v-mean_nz)/std, 0) == 0 identically,
// because mean_nz is the mean of exactly the entries being centered. Hence
// out[b] = relu(fc_b) for every graph, independent of x/edges/weights/passes.
// Verified: rel_err == 0.0 on hardware (rounds 1-2, both sides agree).
//
// We are at the single-kernel graph-replay floor (DRAM 0%, issue 1.7%).
// This round only trims launch cost: one 32-thread warp, minimal body.
// ---------------------------------------------------------------------------

__global__ __launch_bounds__(32) void analytic_out_kernel(
    const float* __restrict__ fcb, float* __restrict__ out, int n)
{
    float r = fmaxf(__ldg(fcb), 0.0f);
    int i = threadIdx.x;
    if (i < n) out[i] = r;
}

extern "C" void kernel_launch(void* const* d_in, const int* in_sizes, int n_in,
                              void* d_out, int out_size)
{
    // metadata order: x, edge_weight, src, dst, dm_indices, fc_w, fc_b, ...
    const float* fcb = (const float*)d_in[6];
    float* out = (float*)d_out;

    if (out_size <= 32) {
        analytic_out_kernel<<<1, 32>>>(fcb, out, out_size);
    } else {
        analytic_out_kernel<<<(out_size + 31) / 32, 32>>>(fcb, out, out_size);
    }
}